// round 6
// baseline (speedup 1.0000x reference)
#include <cuda_runtime.h>
#include <math.h>
#include <stdint.h>

#define B_    256
#define NIN_  6912
#define SLOTS 8

#define NPB   24      // n per block
#define NST   2       // n per stage
#define NSTG  (NPB / NST)   // 12 stages
#define NBUF  3

typedef unsigned long long ull;

#define FFMA2(d, a, b, c) \
    asm("fma.rn.f32x2 %0, %1, %2, %3;" : "=l"(d) : "l"(a), "l"(b), "l"(c))
#define FMUL2(d, a, b) \
    asm("mul.rn.f32x2 %0, %1, %2;" : "=l"(d) : "l"(a), "l"(b))
#define PACK2(d, lo, hi) \
    asm("mov.b64 %0, {%1, %2};" : "=l"(d) : "f"(lo), "f"(hi))
#define UNPACK2(lo, hi, v) \
    asm("mov.b64 {%0, %1}, %2;" : "=f"(lo), "=f"(hi) : "l"(v))

__device__ __forceinline__ uint32_t s2u(const void* p) {
    return (uint32_t)__cvta_generic_to_shared(p);
}
__device__ __forceinline__ void cp16(const void* sdst, const void* gsrc) {
    asm volatile("cp.async.cg.shared.global [%0], [%1], 16;"
                 :: "r"(s2u(sdst)), "l"(gsrc) : "memory");
}
#define CP_COMMIT() asm volatile("cp.async.commit_group;" ::: "memory")
template <int N>
__device__ __forceinline__ void cp_wait() {
    asm volatile("cp.async.wait_group %0;" :: "n"(N) : "memory");
}

// Scratch: s1/s2 transposed [slot][k][b]; v1 [b][k] for vector reads.
__device__ float g_s1[SLOTS * B_ * 32];
__device__ float g_s2[SLOTS * B_ * 32];
__device__ __align__(16) float g_v1[B_ * 32];

__global__ void zero_kernel() {
    int i = blockIdx.x * blockDim.x + threadIdx.x;
    if (i < SLOTS * B_ * 32) { g_s1[i] = 0.0f; g_s2[i] = 0.0f; }
}

__device__ __forceinline__ void squash16(const float* s, float* v) {
    float n2 = 0.0f;
#pragma unroll
    for (int e = 0; e < 16; ++e) n2 = fmaf(s[e], s[e], n2);
    float f = n2 / ((1.0f + n2) * sqrtf(n2 + 1e-9f));
#pragma unroll
    for (int e = 0; e < 16; ++e) v[e] = s[e] * f;
}

// ======================= Pass 1 =======================
// 128 threads: j = tid&1, bp = tid>>1 -> b = {2bp, 2bp+1}. 24 n per block,
// 12 stages x 2 n, 3-buffer cp.async pipeline, 1 sync per stage.
#define P1_THR 128

__global__ __launch_bounds__(P1_THR, 4) void pass1_kernel(const float4* __restrict__ X,
                                                          const float4* __restrict__ Wg) {
    __shared__ float4 Wd[NBUF][NST][16][2][2];        // [buf][nl][e][h][j]
    __shared__ float4 xs[NBUF][128][NST * 2 + 1];     // [buf][bl][nl*2+h], 16B row pad

    const int tid   = threadIdx.x;
    const int j     = tid & 1;
    const int bp    = tid >> 1;
    const int lb0   = bp * 2, lb1 = bp * 2 + 1;
    const int gbb   = blockIdx.y * 128;
    const int nbase = blockIdx.x * NPB;

    ull acc0[16], acc1[16];
    ull zero; PACK2(zero, 0.0f, 0.0f);
#pragma unroll
    for (int e = 0; e < 16; ++e) { acc0[e] = zero; acc1[e] = zero; }

    auto issue = [&](int s) {
        const int buf = s % NBUF;
        const int n0  = nbase + s * NST;
        {   // W: 128 float4 per stage, 1 per thread
            int f  = tid;
            int jj = f & 1, h = (f >> 1) & 1, e = (f >> 2) & 15, nl = (f >> 6) & 1;
            cp16(&Wd[buf][nl][e][h][jj],
                 Wg + ((size_t)(jj * NIN_ + n0 + nl) * 16 + e) * 2 + h);
        }
#pragma unroll
        for (int it = 0; it < 4; ++it) {   // x: 512 float4, 4 per thread
            int f = it * P1_THR + tid;
            int bl = f >> 2, q = f & 3, nl = q >> 1, h = q & 1;
            cp16(&xs[buf][bl][q],
                 X + ((size_t)(gbb + bl) * NIN_ + n0 + nl) * 2 + h);
        }
        CP_COMMIT();
    };

    auto compute = [&](int s) {
        const int buf = s % NBUF;
#pragma unroll
        for (int nl = 0; nl < NST; ++nl) {
            const ulonglong2 xa0 = *reinterpret_cast<const ulonglong2*>(&xs[buf][lb0][nl * 2]);
            const ulonglong2 xa1 = *reinterpret_cast<const ulonglong2*>(&xs[buf][lb0][nl * 2 + 1]);
            const ulonglong2 xb0 = *reinterpret_cast<const ulonglong2*>(&xs[buf][lb1][nl * 2]);
            const ulonglong2 xb1 = *reinterpret_cast<const ulonglong2*>(&xs[buf][lb1][nl * 2 + 1]);
#pragma unroll
            for (int e = 0; e < 16; ++e) {
                const ulonglong2 wA = *reinterpret_cast<const ulonglong2*>(&Wd[buf][nl][e][0][j]);
                const ulonglong2 wB = *reinterpret_cast<const ulonglong2*>(&Wd[buf][nl][e][1][j]);
                ull a = acc0[e];
                FFMA2(a, wA.x, xa0.x, a); FFMA2(a, wA.y, xa0.y, a);
                FFMA2(a, wB.x, xa1.x, a); FFMA2(a, wB.y, xa1.y, a);
                acc0[e] = a;
                ull b = acc1[e];
                FFMA2(b, wA.x, xb0.x, b); FFMA2(b, wA.y, xb0.y, b);
                FFMA2(b, wB.x, xb1.x, b); FFMA2(b, wB.y, xb1.y, b);
                acc1[e] = b;
            }
        }
    };

    issue(0);
    issue(1);
#pragma unroll 3
    for (int s = 0; s < NSTG; ++s) {
        cp_wait<1>();
        __syncthreads();
        compute(s);
        if (s + 2 < NSTG) issue(s + 2); else CP_COMMIT();
    }

    float* dst = g_s1 + (blockIdx.x & (SLOTS - 1)) * (B_ * 32);
#pragma unroll
    for (int e = 0; e < 16; ++e) {
        float lo, hi;
        UNPACK2(lo, hi, acc0[e]);
        atomicAdd(dst + (j * 16 + e) * B_ + gbb + lb0, lo + hi);
        UNPACK2(lo, hi, acc1[e]);
        atomicAdd(dst + (j * 16 + e) * B_ + gbb + lb1, lo + hi);
    }
}

// ======================= v1 = squash(0.5 * sum_slots s1) =======================
__global__ void v1_kernel() {
    const int b = threadIdx.x;
    float s[32];
#pragma unroll
    for (int k = 0; k < 32; ++k) s[k] = 0.0f;
#pragma unroll
    for (int sl = 0; sl < SLOTS; ++sl)
#pragma unroll
        for (int k = 0; k < 32; ++k)
            s[k] += g_s1[sl * (B_ * 32) + k * B_ + b];
#pragma unroll
    for (int k = 0; k < 32; ++k) s[k] *= 0.5f;
    float v[32];
    squash16(s, v);
    squash16(s + 16, v + 16);
#pragma unroll
    for (int k = 0; k < 32; ++k) g_v1[b * 32 + k] = v[k];
}

// ======================= Pass 2 =======================
// 256 threads: j = tid&1, bl = tid>>1 (128 b per block). 24 n per block,
// 12 stages x 2 n, 3-buffer pipeline, 1 sync per stage.
#define P2_THR 256

__global__ __launch_bounds__(P2_THR, 2) void pass2_kernel(const float4* __restrict__ X,
                                                          const float4* __restrict__ Wg) {
    __shared__ float4 Wd[NBUF][NST][16][2][2];
    __shared__ float4 xs[NBUF][128][NST * 2 + 1];

    const int tid   = threadIdx.x;
    const int j     = tid & 1;
    const int bl    = tid >> 1;
    const int gbb   = blockIdx.y * 128;
    const int b     = gbb + bl;
    const int nbase = blockIdx.x * NPB;

    // v1 for (b, j), packed into e-pairs
    ull v1p[8];
    {
        const float4* vp = reinterpret_cast<const float4*>(g_v1 + b * 32 + j * 16);
#pragma unroll
        for (int q = 0; q < 4; ++q) {
            float4 v = vp[q];
            PACK2(v1p[2 * q],     v.x, v.y);
            PACK2(v1p[2 * q + 1], v.z, v.w);
        }
    }

    ull accp[8];
    ull zero; PACK2(zero, 0.0f, 0.0f);
#pragma unroll
    for (int q = 0; q < 8; ++q) accp[q] = zero;

    auto issue = [&](int s) {
        const int buf = s % NBUF;
        const int n0  = nbase + s * NST;
        if (tid < 128) {   // W: 128 float4 per stage
            int f  = tid;
            int jj = f & 1, h = (f >> 1) & 1, e = (f >> 2) & 15, nl = (f >> 6) & 1;
            cp16(&Wd[buf][nl][e][h][jj],
                 Wg + ((size_t)(jj * NIN_ + n0 + nl) * 16 + e) * 2 + h);
        }
#pragma unroll
        for (int it = 0; it < 2; ++it) {   // x: 512 float4, 2 per thread
            int f = it * P2_THR + tid;
            int b2 = f >> 2, q = f & 3, nl = q >> 1, h = q & 1;
            cp16(&xs[buf][b2][q],
                 X + ((size_t)(gbb + b2) * NIN_ + n0 + nl) * 2 + h);
        }
        CP_COMMIT();
    };

    auto compute = [&](int s) {
        const int buf = s % NBUF;
#pragma unroll
        for (int nl = 0; nl < NST; ++nl) {
            const ulonglong2 x0 = *reinterpret_cast<const ulonglong2*>(&xs[buf][bl][nl * 2]);
            const ulonglong2 x1 = *reinterpret_cast<const ulonglong2*>(&xs[buf][bl][nl * 2 + 1]);

            float u[16];
#pragma unroll
            for (int e = 0; e < 16; ++e) {
                const ulonglong2 wA = *reinterpret_cast<const ulonglong2*>(&Wd[buf][nl][e][0][j]);
                const ulonglong2 wB = *reinterpret_cast<const ulonglong2*>(&Wd[buf][nl][e][1][j]);
                ull t;
                FMUL2(t, wA.x, x0.x);
                FFMA2(t, wA.y, x0.y, t);
                FFMA2(t, wB.x, x1.x, t);
                FFMA2(t, wB.y, x1.y, t);
                float lo, hi;
                UNPACK2(lo, hi, t);
                u[e] = lo + hi;
            }

            ull up[8];
            ull t2 = zero;
#pragma unroll
            for (int q = 0; q < 8; ++q) {
                PACK2(up[q], u[2 * q], u[2 * q + 1]);
                FFMA2(t2, v1p[q], up[q], t2);
            }
            float tlo, thi;
            UNPACK2(tlo, thi, t2);
            float tj = tlo + thi;
            float to = __shfl_xor_sync(0xffffffffu, tj, 1);
            float c  = __fdividef(1.0f, 1.0f + __expf(to - tj));
            ull cd; PACK2(cd, c, c);
#pragma unroll
            for (int q = 0; q < 8; ++q)
                FFMA2(accp[q], cd, up[q], accp[q]);
        }
    };

    issue(0);
    issue(1);
#pragma unroll 3
    for (int s = 0; s < NSTG; ++s) {
        cp_wait<1>();
        __syncthreads();
        compute(s);
        if (s + 2 < NSTG) issue(s + 2); else CP_COMMIT();
    }

    float* dst = g_s2 + (blockIdx.x & (SLOTS - 1)) * (B_ * 32);
#pragma unroll
    for (int q = 0; q < 8; ++q) {
        float lo, hi;
        UNPACK2(lo, hi, accp[q]);
        atomicAdd(dst + (j * 16 + 2 * q) * B_ + b,     lo);
        atomicAdd(dst + (j * 16 + 2 * q + 1) * B_ + b, hi);
    }
}

// ======================= Output =======================
__global__ void squash_out_kernel(float* __restrict__ out) {
    int t = blockIdx.x * blockDim.x + threadIdx.x;   // t = b*2 + j
    if (t < B_ * 2) {
        int b = t >> 1, j = t & 1;
        float s[16];
#pragma unroll
        for (int e = 0; e < 16; ++e) s[e] = 0.0f;
#pragma unroll
        for (int sl = 0; sl < SLOTS; ++sl)
#pragma unroll
            for (int e = 0; e < 16; ++e)
                s[e] += g_s2[sl * (B_ * 32) + (j * 16 + e) * B_ + b];
        float v[16];
        squash16(s, v);
#pragma unroll
        for (int e = 0; e < 16; ++e) out[t * 16 + e] = v[e];
    }
}

extern "C" void kernel_launch(void* const* d_in, const int* in_sizes, int n_in,
                              void* d_out, int out_size) {
    const float4* X = (const float4*)d_in[0];   // x: [256, 6912, 8] f32
    const float4* W = (const float4*)d_in[1];   // W: [2, 6912, 16, 8] f32
    float* out = (float*)d_out;                 // v: [256, 2, 16] f32

    zero_kernel<<<(SLOTS * B_ * 32 + 255) / 256, 256>>>();

    dim3 g1(NIN_ / NPB, B_ / 128);   // 288 x 2
    pass1_kernel<<<g1, P1_THR>>>(X, W);

    v1_kernel<<<1, B_>>>();

    dim3 g2(NIN_ / NPB, B_ / 128);   // 288 x 2
    pass2_kernel<<<g2, P2_THR>>>(X, W);

    squash_out_kernel<<<2, 256>>>(out);
}

// round 7
// speedup vs baseline: 1.1005x; 1.1005x over previous
#include <cuda_runtime.h>
#include <math.h>
#include <stdint.h>

#define B_    256
#define NIN_  6912
#define SLOTS 8

#define NPB   24            // n per block
#define NST   2             // n per stage
#define NSTG  (NPB / NST)   // 12 stages
#define NBUF  3

typedef unsigned long long ull;

#define FFMA2(d, a, b, c) \
    asm("fma.rn.f32x2 %0, %1, %2, %3;" : "=l"(d) : "l"(a), "l"(b), "l"(c))
#define FMUL2(d, a, b) \
    asm("mul.rn.f32x2 %0, %1, %2;" : "=l"(d) : "l"(a), "l"(b))
#define PACK2(d, lo, hi) \
    asm("mov.b64 %0, {%1, %2};" : "=l"(d) : "f"(lo), "f"(hi))
#define UNPACK2(lo, hi, v) \
    asm("mov.b64 {%0, %1}, %2;" : "=f"(lo), "=f"(hi) : "l"(v))

__device__ __forceinline__ uint32_t s2u(const void* p) {
    return (uint32_t)__cvta_generic_to_shared(p);
}
__device__ __forceinline__ void cp16(const void* sdst, const void* gsrc) {
    asm volatile("cp.async.cg.shared.global [%0], [%1], 16;"
                 :: "r"(s2u(sdst)), "l"(gsrc) : "memory");
}
#define CP_COMMIT() asm volatile("cp.async.commit_group;" ::: "memory")
template <int N>
__device__ __forceinline__ void cp_wait() {
    asm volatile("cp.async.wait_group %0;" :: "n"(N) : "memory");
}

// Scratch: s1/s2 transposed [slot][k][b] (k=j*16+e); v1 [b][k].
__device__ float g_s1[SLOTS * B_ * 32];
__device__ float g_s2[SLOTS * B_ * 32];
__device__ __align__(16) float g_v1[B_ * 32];

__global__ void zero_kernel() {
    int i = blockIdx.x * blockDim.x + threadIdx.x;
    if (i < SLOTS * B_ * 32) { g_s1[i] = 0.0f; g_s2[i] = 0.0f; }
}

__device__ __forceinline__ void squash16(const float* s, float* v) {
    float n2 = 0.0f;
#pragma unroll
    for (int e = 0; e < 16; ++e) n2 = fmaf(s[e], s[e], n2);
    float f = n2 / ((1.0f + n2) * sqrtf(n2 + 1e-9f));
#pragma unroll
    for (int e = 0; e < 16; ++e) v[e] = s[e] * f;
}

// ======================= Pass 1 =======================
// 128 threads: j = tid&1, bp = tid>>1 -> b = {2bp, 2bp+1}. 24 n per block,
// 12 stages x 2 n, 3-buffer cp.async pipeline, 1 sync per stage.
#define P1_THR 128

__global__ __launch_bounds__(P1_THR, 4) void pass1_kernel(const float4* __restrict__ X,
                                                          const float4* __restrict__ Wg) {
    __shared__ float4 Wd[NBUF][NST][16][2][2];        // [buf][nl][e][h][j]
    __shared__ float4 xs[NBUF][128][NST * 2 + 1];     // [buf][bl][nl*2+h]

    const int tid   = threadIdx.x;
    const int j     = tid & 1;
    const int bp    = tid >> 1;
    const int lb0   = bp * 2, lb1 = bp * 2 + 1;
    const int gbb   = blockIdx.y * 128;
    const int nbase = blockIdx.x * NPB;

    ull acc0[16], acc1[16];
    ull zero; PACK2(zero, 0.0f, 0.0f);
#pragma unroll
    for (int e = 0; e < 16; ++e) { acc0[e] = zero; acc1[e] = zero; }

    auto issue = [&](int s) {
        const int buf = s % NBUF;
        const int n0  = nbase + s * NST;
        {   // W: 128 float4 per stage, 1 per thread
            int f  = tid;
            int jj = f & 1, h = (f >> 1) & 1, e = (f >> 2) & 15, nl = (f >> 6) & 1;
            cp16(&Wd[buf][nl][e][h][jj],
                 Wg + ((size_t)(jj * NIN_ + n0 + nl) * 16 + e) * 2 + h);
        }
#pragma unroll
        for (int it = 0; it < 4; ++it) {   // x: 512 float4, 4 per thread
            int f = it * P1_THR + tid;
            int bl = f >> 2, q = f & 3, nl = q >> 1, h = q & 1;
            cp16(&xs[buf][bl][q],
                 X + ((size_t)(gbb + bl) * NIN_ + n0 + nl) * 2 + h);
        }
        CP_COMMIT();
    };

    auto compute = [&](int s) {
        const int buf = s % NBUF;
#pragma unroll
        for (int nl = 0; nl < NST; ++nl) {
            const ulonglong2 xa0 = *reinterpret_cast<const ulonglong2*>(&xs[buf][lb0][nl * 2]);
            const ulonglong2 xa1 = *reinterpret_cast<const ulonglong2*>(&xs[buf][lb0][nl * 2 + 1]);
            const ulonglong2 xb0 = *reinterpret_cast<const ulonglong2*>(&xs[buf][lb1][nl * 2]);
            const ulonglong2 xb1 = *reinterpret_cast<const ulonglong2*>(&xs[buf][lb1][nl * 2 + 1]);
#pragma unroll
            for (int e = 0; e < 16; ++e) {
                const ulonglong2 wA = *reinterpret_cast<const ulonglong2*>(&Wd[buf][nl][e][0][j]);
                const ulonglong2 wB = *reinterpret_cast<const ulonglong2*>(&Wd[buf][nl][e][1][j]);
                ull a = acc0[e];
                FFMA2(a, wA.x, xa0.x, a); FFMA2(a, wA.y, xa0.y, a);
                FFMA2(a, wB.x, xa1.x, a); FFMA2(a, wB.y, xa1.y, a);
                acc0[e] = a;
                ull b = acc1[e];
                FFMA2(b, wA.x, xb0.x, b); FFMA2(b, wA.y, xb0.y, b);
                FFMA2(b, wB.x, xb1.x, b); FFMA2(b, wB.y, xb1.y, b);
                acc1[e] = b;
            }
        }
    };

    issue(0);
    issue(1);
#pragma unroll 3
    for (int s = 0; s < NSTG; ++s) {
        cp_wait<1>();
        __syncthreads();
        compute(s);
        if (s + 2 < NSTG) issue(s + 2); else CP_COMMIT();
    }

    float* dst = g_s1 + (blockIdx.x & (SLOTS - 1)) * (B_ * 32);
#pragma unroll
    for (int e = 0; e < 16; ++e) {
        float lo, hi;
        UNPACK2(lo, hi, acc0[e]);
        atomicAdd(dst + (j * 16 + e) * B_ + gbb + lb0, lo + hi);
        UNPACK2(lo, hi, acc1[e]);
        atomicAdd(dst + (j * 16 + e) * B_ + gbb + lb1, lo + hi);
    }
}

// ======================= v1 = squash(0.5 * sum_slots s1) =======================
// 1024 threads: phase 1 parallel slot-sum (coalesced), phase 2 squash from smem.
__global__ void v1_kernel() {
    __shared__ float s[32][B_];
    const int tid = threadIdx.x;
    const int b   = tid & 255;
    const int kg  = tid >> 8;           // 0..3
#pragma unroll
    for (int i = 0; i < 8; ++i) {
        int k = kg * 8 + i;
        float a = 0.0f;
#pragma unroll
        for (int sl = 0; sl < SLOTS; ++sl)
            a += g_s1[sl * (B_ * 32) + k * B_ + b];
        s[k][b] = a * 0.5f;
    }
    __syncthreads();
    if (tid < 512) {
        int bb = tid >> 1, j = tid & 1;
        float sv[16], v[16];
#pragma unroll
        for (int e = 0; e < 16; ++e) sv[e] = s[j * 16 + e][bb];
        squash16(sv, v);
#pragma unroll
        for (int e = 0; e < 16; ++e) g_v1[bb * 32 + j * 16 + e] = v[e];
    }
}

// ======================= Pass 2 =======================
// 256 threads: j = tid&1, bl = tid>>1 (128 b). 24 n per block, 12 stages x 2 n.
// The two n of each stage are processed with interleaved (overlapping)
// logit->shfl->exp chains to hide the per-n serial latency.
#define P2_THR 256

__global__ __launch_bounds__(P2_THR, 2) void pass2_kernel(const float4* __restrict__ X,
                                                          const float4* __restrict__ Wg) {
    __shared__ float4 Wd[NBUF][NST][16][2][2];
    __shared__ float4 xs[NBUF][128][NST * 2 + 1];

    const int tid   = threadIdx.x;
    const int j     = tid & 1;
    const int bl    = tid >> 1;
    const int gbb   = blockIdx.y * 128;
    const int b     = gbb + bl;
    const int nbase = blockIdx.x * NPB;

    // v1 for (b, j), packed into e-pairs
    ull v1p[8];
    {
        const float4* vp = reinterpret_cast<const float4*>(g_v1 + b * 32 + j * 16);
#pragma unroll
        for (int q = 0; q < 4; ++q) {
            float4 v = vp[q];
            PACK2(v1p[2 * q],     v.x, v.y);
            PACK2(v1p[2 * q + 1], v.z, v.w);
        }
    }

    ull accp[8];
    ull zero; PACK2(zero, 0.0f, 0.0f);
#pragma unroll
    for (int q = 0; q < 8; ++q) accp[q] = zero;

    auto issue = [&](int s) {
        const int buf = s % NBUF;
        const int n0  = nbase + s * NST;
        if (tid < 128) {   // W: 128 float4 per stage
            int f  = tid;
            int jj = f & 1, h = (f >> 1) & 1, e = (f >> 2) & 15, nl = (f >> 6) & 1;
            cp16(&Wd[buf][nl][e][h][jj],
                 Wg + ((size_t)(jj * NIN_ + n0 + nl) * 16 + e) * 2 + h);
        }
#pragma unroll
        for (int it = 0; it < 2; ++it) {   // x: 512 float4, 2 per thread
            int f = it * P2_THR + tid;
            int b2 = f >> 2, q = f & 3, nl = q >> 1, h = q & 1;
            cp16(&xs[buf][b2][q],
                 X + ((size_t)(gbb + b2) * NIN_ + n0 + nl) * 2 + h);
        }
        CP_COMMIT();
    };

    auto compute = [&](int s) {
        const int buf = s % NBUF;
        ull up[NST][8];
        float tj[NST];

        // Phase A: u + logit partials for BOTH n (independent -> ILP)
#pragma unroll
        for (int nl = 0; nl < NST; ++nl) {
            const ulonglong2 x0 = *reinterpret_cast<const ulonglong2*>(&xs[buf][bl][nl * 2]);
            const ulonglong2 x1 = *reinterpret_cast<const ulonglong2*>(&xs[buf][bl][nl * 2 + 1]);
            ull t2 = zero;
#pragma unroll
            for (int q = 0; q < 8; ++q) {
                const int e0 = 2 * q, e1 = 2 * q + 1;
                const ulonglong2 wA0 = *reinterpret_cast<const ulonglong2*>(&Wd[buf][nl][e0][0][j]);
                const ulonglong2 wB0 = *reinterpret_cast<const ulonglong2*>(&Wd[buf][nl][e0][1][j]);
                const ulonglong2 wA1 = *reinterpret_cast<const ulonglong2*>(&Wd[buf][nl][e1][0][j]);
                const ulonglong2 wB1 = *reinterpret_cast<const ulonglong2*>(&Wd[buf][nl][e1][1][j]);
                ull ta, tb;
                FMUL2(ta, wA0.x, x0.x);
                FFMA2(ta, wA0.y, x0.y, ta);
                FFMA2(ta, wB0.x, x1.x, ta);
                FFMA2(ta, wB0.y, x1.y, ta);
                FMUL2(tb, wA1.x, x0.x);
                FFMA2(tb, wA1.y, x0.y, tb);
                FFMA2(tb, wB1.x, x1.x, tb);
                FFMA2(tb, wB1.y, x1.y, tb);
                float alo, ahi, blo, bhi;
                UNPACK2(alo, ahi, ta);
                UNPACK2(blo, bhi, tb);
                ull u;
                PACK2(u, alo + ahi, blo + bhi);
                up[nl][q] = u;
                FFMA2(t2, v1p[q], u, t2);
            }
            float tlo, thi;
            UNPACK2(tlo, thi, t2);
            tj[nl] = tlo + thi;
        }

        // Phase B: both shfl/exp/div chains issued back-to-back (overlap)
        float c[NST];
#pragma unroll
        for (int nl = 0; nl < NST; ++nl) {
            float to = __shfl_xor_sync(0xffffffffu, tj[nl], 1);
            c[nl] = __fdividef(1.0f, 1.0f + __expf(to - tj[nl]));
        }

        // Phase C: accumulate
#pragma unroll
        for (int nl = 0; nl < NST; ++nl) {
            ull cd; PACK2(cd, c[nl], c[nl]);
#pragma unroll
            for (int q = 0; q < 8; ++q)
                FFMA2(accp[q], cd, up[nl][q], accp[q]);
        }
    };

    issue(0);
    issue(1);
#pragma unroll 3
    for (int s = 0; s < NSTG; ++s) {
        cp_wait<1>();
        __syncthreads();
        compute(s);
        if (s + 2 < NSTG) issue(s + 2); else CP_COMMIT();
    }

    float* dst = g_s2 + (blockIdx.x & (SLOTS - 1)) * (B_ * 32);
#pragma unroll
    for (int q = 0; q < 8; ++q) {
        float lo, hi;
        UNPACK2(lo, hi, accp[q]);
        atomicAdd(dst + (j * 16 + 2 * q) * B_ + b,     lo);
        atomicAdd(dst + (j * 16 + 2 * q + 1) * B_ + b, hi);
    }
}

// ======================= Output: v = squash(sum_slots s2) =======================
__global__ void squash_out_kernel(float* __restrict__ out) {
    __shared__ float s[32][B_];
    const int tid = threadIdx.x;
    const int b   = tid & 255;
    const int kg  = tid >> 8;
#pragma unroll
    for (int i = 0; i < 8; ++i) {
        int k = kg * 8 + i;
        float a = 0.0f;
#pragma unroll
        for (int sl = 0; sl < SLOTS; ++sl)
            a += g_s2[sl * (B_ * 32) + k * B_ + b];
        s[k][b] = a;
    }
    __syncthreads();
    if (tid < 512) {
        int bb = tid >> 1, j = tid & 1;
        float sv[16], v[16];
#pragma unroll
        for (int e = 0; e < 16; ++e) sv[e] = s[j * 16 + e][bb];
        squash16(sv, v);
#pragma unroll
        for (int e = 0; e < 16; ++e) out[bb * 32 + j * 16 + e] = v[e];
    }
}

extern "C" void kernel_launch(void* const* d_in, const int* in_sizes, int n_in,
                              void* d_out, int out_size) {
    const float4* X = (const float4*)d_in[0];   // x: [256, 6912, 8] f32
    const float4* W = (const float4*)d_in[1];   // W: [2, 6912, 16, 8] f32
    float* out = (float*)d_out;                 // v: [256, 2, 16] f32

    zero_kernel<<<(SLOTS * B_ * 32 + 255) / 256, 256>>>();

    dim3 g1(NIN_ / NPB, B_ / 128);   // 288 x 2
    pass1_kernel<<<g1, P1_THR>>>(X, W);

    v1_kernel<<<1, 1024>>>();

    dim3 g2(NIN_ / NPB, B_ / 128);   // 288 x 2
    pass2_kernel<<<g2, P2_THR>>>(X, W);

    squash_out_kernel<<<1, 1024>>>(out);
}